// round 2
// baseline (speedup 1.0000x reference)
#include <cuda_runtime.h>

// Problem constants (fixed by the reference)
#define NN 100000
#define NE 1600000

// Scratch (device globals — no allocation allowed in kernel_launch)
__device__ int g_is64;               // 1 if edge_index buffer is int64, 0 if int32
__device__ __align__(16) float g_deg [NN];
__device__ __align__(16) float g_dinv[NN];
__device__ __align__(16) float g_hs  [NN * 64];  // dinv-scaled features (layer reuse)
__device__ __align__(16) float g_acc [NN * 64];  // scatter accumulator (layer reuse)
__device__ __align__(16) float g_x   [NN * 64];  // layer output / next-layer input

// Read edge index element `pos` (pos in [0, 2*NE)), dtype-agnostic.
__device__ __forceinline__ int eidx(const void* __restrict__ ei, long long pos) {
    if (g_is64) return (int)((const long long*)ei)[pos];
    return ((const int*)ei)[pos];
}

// ---------------------------------------------------------------------------
// Detect int64 vs int32 layout: if int64, every odd 32-bit word (high half of
// a nonneg 64-bit index < 2^31) is zero. Sample 48 odd words.
// ---------------------------------------------------------------------------
__global__ void k_detect(const int* __restrict__ ei32) {
    if (threadIdx.x == 0) {
        int all_zero = 1;
        for (int k = 0; k < 48; k++) {
            if (ei32[2 * k + 1] != 0) { all_zero = 0; break; }
        }
        g_is64 = all_zero;
    }
}

// ---------------------------------------------------------------------------
// Degree: deg[i] = 1 (self loop) + indeg(i);  dinv = rsqrt(deg)
// ---------------------------------------------------------------------------
__global__ void k_initdeg() {
    int i = blockIdx.x * blockDim.x + threadIdx.x;
    if (i < NN) g_deg[i] = 1.0f;
}

__global__ void k_count(const void* __restrict__ ei) {
    int e = blockIdx.x * blockDim.x + threadIdx.x;
    if (e < NE) {
        int dst = eidx(ei, (long long)NE + e);
        atomicAdd(&g_deg[dst], 1.0f);
    }
}

__global__ void k_dinv() {
    int i = blockIdx.x * blockDim.x + threadIdx.x;
    if (i < NN) g_dinv[i] = rsqrtf(g_deg[i]);
}

// ---------------------------------------------------------------------------
// Layer 1 transform: h = X(5) @ W1(5x64); hs = h*dinv; acc = hs (self loop)
// One thread computes 4 contiguous outputs (float4 stores).
// ---------------------------------------------------------------------------
__global__ void k_transform1(const float* __restrict__ x,
                             const float* __restrict__ W) {
    int t = blockIdx.x * blockDim.x + threadIdx.x;
    if (t >= NN * 16) return;
    int i = t >> 4;
    int g = (t & 15) * 4;

    float xv[5];
#pragma unroll
    for (int k = 0; k < 5; k++) xv[k] = x[i * 5 + k];

    float a0 = 0.f, a1 = 0.f, a2 = 0.f, a3 = 0.f;
#pragma unroll
    for (int k = 0; k < 5; k++) {
        const float* w = &W[k * 64 + g];
        a0 = fmaf(xv[k], w[0], a0);
        a1 = fmaf(xv[k], w[1], a1);
        a2 = fmaf(xv[k], w[2], a2);
        a3 = fmaf(xv[k], w[3], a3);
    }
    float d = g_dinv[i];
    float4 v = make_float4(a0 * d, a1 * d, a2 * d, a3 * d);
    *(float4*)&g_hs [i * 64 + g] = v;
    *(float4*)&g_acc[i * 64 + g] = v;
}

// ---------------------------------------------------------------------------
// Edge scatter: acc[dst*F + f] += hs[src*F + f]
// F/4 threads per edge; each does one 16B gather + one red.global.add.v4.f32.
// ---------------------------------------------------------------------------
template <int F>
__global__ void k_scatter(const void* __restrict__ ei) {
    constexpr int F4 = F / 4;
    int t = blockIdx.x * blockDim.x + threadIdx.x;
    if (t >= NE * F4) return;
    int e = t / F4;
    int p = (t % F4) * 4;
    int src = eidx(ei, e);
    int dst = eidx(ei, (long long)NE + e);
    float4 v = *(const float4*)&g_hs[src * F + p];
    float* a = &g_acc[dst * F + p];
    asm volatile("red.global.add.v4.f32 [%0], {%1,%2,%3,%4};"
                 :: "l"(a), "f"(v.x), "f"(v.y), "f"(v.z), "f"(v.w)
                 : "memory");
}

// ---------------------------------------------------------------------------
// Layer 1 finalize: x1 = relu(acc * dinv + b1)   (64-wide)
// ---------------------------------------------------------------------------
__global__ void k_finalize1(const float* __restrict__ b) {
    int t = blockIdx.x * blockDim.x + threadIdx.x;
    if (t >= NN * 16) return;
    int i = t >> 4;
    int g = (t & 15) * 4;
    float d = g_dinv[i];
    float4 a = *(const float4*)&g_acc[i * 64 + g];
    float4 o;
    o.x = fmaxf(fmaf(a.x, d, b[g + 0]), 0.f);
    o.y = fmaxf(fmaf(a.y, d, b[g + 1]), 0.f);
    o.z = fmaxf(fmaf(a.z, d, b[g + 2]), 0.f);
    o.w = fmaxf(fmaf(a.w, d, b[g + 3]), 0.f);
    *(float4*)&g_x[i * 64 + g] = o;
}

// ---------------------------------------------------------------------------
// Layer 2 transform: h = x1(64) @ W2(64x32); hs = h*dinv; acc = hs
// One warp per node: x1[k] is a broadcast load, W2[k*32+lane] coalesced.
// ---------------------------------------------------------------------------
__global__ void k_transform2(const float* __restrict__ W2) {
    int warp = (blockIdx.x * blockDim.x + threadIdx.x) >> 5;
    int lane = threadIdx.x & 31;
    if (warp >= NN) return;
    const float* xr = &g_x[warp * 64];
    float s = 0.f;
#pragma unroll 8
    for (int k = 0; k < 64; k++)
        s = fmaf(xr[k], W2[k * 32 + lane], s);
    float hs = s * g_dinv[warp];
    g_hs [warp * 32 + lane] = hs;
    g_acc[warp * 32 + lane] = hs;
}

// ---------------------------------------------------------------------------
// Layer 2 finalize fused with the MLP head:
// x2 = relu(acc*dinv + b2); x3 = relu(x2@fcW1 + fcb1); out = x3@fcW2 + fcb2
// One thread per node (576 FMAs — negligible).
// ---------------------------------------------------------------------------
__global__ void k_final2(const float* __restrict__ b2,
                         const float* __restrict__ fcW1,
                         const float* __restrict__ fcb1,
                         const float* __restrict__ fcW2,
                         const float* __restrict__ fcb2,
                         float* __restrict__ out) {
    int i = blockIdx.x * blockDim.x + threadIdx.x;
    if (i >= NN) return;
    float d = g_dinv[i];

    float x2[32];
#pragma unroll
    for (int j = 0; j < 32; j += 4) {
        float4 a = *(const float4*)&g_acc[i * 32 + j];
        x2[j + 0] = fmaxf(fmaf(a.x, d, b2[j + 0]), 0.f);
        x2[j + 1] = fmaxf(fmaf(a.y, d, b2[j + 1]), 0.f);
        x2[j + 2] = fmaxf(fmaf(a.z, d, b2[j + 2]), 0.f);
        x2[j + 3] = fmaxf(fmaf(a.w, d, b2[j + 3]), 0.f);
    }

    float x3[16];
#pragma unroll
    for (int m = 0; m < 16; m++) x3[m] = fcb1[m];
#pragma unroll
    for (int j = 0; j < 32; j++) {
        float xv = x2[j];
#pragma unroll
        for (int m = 0; m < 16; m++)
            x3[m] = fmaf(xv, fcW1[j * 16 + m], x3[m]);
    }
#pragma unroll
    for (int m = 0; m < 16; m++) x3[m] = fmaxf(x3[m], 0.f);

    float o0 = fcb2[0], o1 = fcb2[1];
#pragma unroll
    for (int m = 0; m < 16; m++) {
        o0 = fmaf(x3[m], fcW2[m * 2 + 0], o0);
        o1 = fmaf(x3[m], fcW2[m * 2 + 1], o1);
    }
    out[i * 2 + 0] = o0;
    out[i * 2 + 1] = o1;
}

// ---------------------------------------------------------------------------
// Launch
// ---------------------------------------------------------------------------
extern "C" void kernel_launch(void* const* d_in, const int* in_sizes, int n_in,
                              void* d_out, int out_size) {
    const float* edge_attr = (const float*)d_in[0];
    const void*  edge_idx  = d_in[1];
    const float* W1   = (const float*)d_in[2];
    const float* b1   = (const float*)d_in[3];
    const float* W2   = (const float*)d_in[4];
    const float* b2   = (const float*)d_in[5];
    const float* fcW1 = (const float*)d_in[6];
    const float* fcb1 = (const float*)d_in[7];
    const float* fcW2 = (const float*)d_in[8];
    const float* fcb2 = (const float*)d_in[9];
    float* out = (float*)d_out;

    const int T = 256;

    // Detect edge_index dtype (int32 vs int64) on-device.
    k_detect<<<1, 32>>>((const int*)edge_idx);

    // Degree / normalization
    k_initdeg<<<(NN + T - 1) / T, T>>>();
    k_count  <<<(NE + T - 1) / T, T>>>(edge_idx);
    k_dinv   <<<(NN + T - 1) / T, T>>>();

    // Layer 1 (5 -> 64)
    k_transform1<<<(NN * 16 + T - 1) / T, T>>>(edge_attr, W1);
    k_scatter<64><<<(NE * 16 + T - 1) / T, T>>>(edge_idx);
    k_finalize1<<<(NN * 16 + T - 1) / T, T>>>(b1);

    // Layer 2 (64 -> 32)
    k_transform2<<<(NN * 32 + T - 1) / T, T>>>(W2);
    k_scatter<32><<<(NE * 8 + T - 1) / T, T>>>(edge_idx);

    // Finalize layer 2 + MLP head (32 -> 16 -> 2)
    k_final2<<<(NN + T - 1) / T, T>>>(b2, fcW1, fcb1, fcW2, fcb2, out);
}

// round 3
// speedup vs baseline: 1.5552x; 1.5552x over previous
#include <cuda_runtime.h>

// Problem constants (fixed by the reference)
#define NN 100000
#define NE 1600000

// Scratch (device globals — no allocation allowed in kernel_launch)
__device__ int g_is64;                    // edge_index dtype flag
__device__ __align__(16) int2  g_edge[NE];       // packed (src, dst), int32
__device__ __align__(16) float g_deg [NN];
__device__ __align__(16) float g_dinv[NN];
__device__ __align__(16) float g_hs1 [NN * 8];   // dinv-scaled raw features (5 used, stride 8)
__device__ __align__(16) float g_acc1[NN * 8];   // layer-1 aggregation accumulator
__device__ __align__(16) float g_hs2 [NN * 32];  // dinv-scaled transformed features (layer 2)
__device__ __align__(16) float g_acc2[NN * 32];  // layer-2 aggregation accumulator

// ---------------------------------------------------------------------------
// Dtype detect: if int64, high words of nonneg indices < 2^31 are all zero.
// ---------------------------------------------------------------------------
__global__ void k_detect(const int* __restrict__ ei32) {
    if (threadIdx.x == 0) {
        int all_zero = 1;
        for (int k = 0; k < 48; k++)
            if (ei32[2 * k + 1] != 0) { all_zero = 0; break; }
        g_is64 = all_zero;
    }
}

__global__ void k_initdeg() {
    int i = blockIdx.x * blockDim.x + threadIdx.x;
    if (i < NN) g_deg[i] = 1.0f;   // self loop
}

// Convert edge index to packed int2 + count in-degree (fused prepass).
__global__ void k_prep(const void* __restrict__ ei) {
    int e = blockIdx.x * blockDim.x + threadIdx.x;
    if (e >= NE) return;
    int src, dst;
    if (g_is64) {
        src = (int)((const long long*)ei)[e];
        dst = (int)((const long long*)ei)[(long long)NE + e];
    } else {
        src = ((const int*)ei)[e];
        dst = ((const int*)ei)[NE + e];
    }
    g_edge[e] = make_int2(src, dst);
    asm volatile("red.global.add.f32 [%0], %1;" :: "l"(&g_deg[dst]), "f"(1.0f) : "memory");
}

__global__ void k_dinv() {
    int i = blockIdx.x * blockDim.x + threadIdx.x;
    if (i < NN) g_dinv[i] = rsqrtf(g_deg[i]);
}

// ---------------------------------------------------------------------------
// Pre-scale raw features: hs1[i] = x[i] * dinv[i]; acc1[i] = hs1[i] (self loop)
// ---------------------------------------------------------------------------
__global__ void k_prescale(const float* __restrict__ x) {
    int i = blockIdx.x * blockDim.x + threadIdx.x;
    if (i >= NN) return;
    float d = g_dinv[i];
    float v0 = x[i * 5 + 0] * d, v1 = x[i * 5 + 1] * d, v2 = x[i * 5 + 2] * d,
          v3 = x[i * 5 + 3] * d, v4 = x[i * 5 + 4] * d;
    float4 q = make_float4(v0, v1, v2, v3);
    *(float4*)&g_hs1 [i * 8] = q;  g_hs1 [i * 8 + 4] = v4;
    *(float4*)&g_acc1[i * 8] = q;  g_acc1[i * 8 + 4] = v4;
}

// ---------------------------------------------------------------------------
// Layer-1 edge aggregation on RAW features (5 floats, stride 8).
// One thread per edge: 8B index + 20B gather + 20B reduce.
// ---------------------------------------------------------------------------
__global__ void k_scatter1() {
    int e = blockIdx.x * blockDim.x + threadIdx.x;
    if (e >= NE) return;
    int2 ed = g_edge[e];
    const float* h = &g_hs1[ed.x * 8];
    float4 v = *(const float4*)h;
    float  v4 = h[4];
    float* a = &g_acc1[ed.y * 8];
    asm volatile("red.global.add.v4.f32 [%0], {%1,%2,%3,%4};"
                 :: "l"(a), "f"(v.x), "f"(v.y), "f"(v.z), "f"(v.w) : "memory");
    asm volatile("red.global.add.f32 [%0], %1;"
                 :: "l"(a + 4), "f"(v4) : "memory");
}

// ---------------------------------------------------------------------------
// Fused middle: per node (one warp):
//   agg = dinv * acc1 (5)        [finalize layer-1 aggregation]
//   x1  = relu(agg @ W1 + b1)    [64, lives in SMEM only]
//   hs2 = (x1 @ W2) * dinv       [32, write + self-loop init of acc2]
// Grid is exactly NN/8 blocks of 8 warps (NN divisible by 8? 100000/8=12500 ✓)
// ---------------------------------------------------------------------------
__global__ void k_mid(const float* __restrict__ W1, const float* __restrict__ b1,
                      const float* __restrict__ W2) {
    __shared__ float sW1[5 * 64];
    __shared__ float sb1[64];
    __shared__ float sW2[64 * 32];
    __shared__ float sx1[8][64];

    int tid = threadIdx.x;             // 256 threads = 8 warps
    for (int k = tid; k < 5 * 64; k += 256) sW1[k] = W1[k];
    if (tid < 64) sb1[tid] = b1[tid];
    for (int k = tid; k < 64 * 32; k += 256) sW2[k] = W2[k];
    __syncthreads();

    int node = blockIdx.x * 8 + (tid >> 5);   // one warp per node
    int lane = tid & 31;
    int wl   = tid >> 5;

    float d = g_dinv[node];
    float a0 = g_acc1[node * 8 + 0] * d;
    float a1 = g_acc1[node * 8 + 1] * d;
    float a2 = g_acc1[node * 8 + 2] * d;
    float a3 = g_acc1[node * 8 + 3] * d;
    float a4 = g_acc1[node * 8 + 4] * d;

    // x1 columns lane and lane+32
    float xa = sb1[lane], xb = sb1[lane + 32];
    xa = fmaf(a0, sW1[0 * 64 + lane], xa);  xb = fmaf(a0, sW1[0 * 64 + lane + 32], xb);
    xa = fmaf(a1, sW1[1 * 64 + lane], xa);  xb = fmaf(a1, sW1[1 * 64 + lane + 32], xb);
    xa = fmaf(a2, sW1[2 * 64 + lane], xa);  xb = fmaf(a2, sW1[2 * 64 + lane + 32], xb);
    xa = fmaf(a3, sW1[3 * 64 + lane], xa);  xb = fmaf(a3, sW1[3 * 64 + lane + 32], xb);
    xa = fmaf(a4, sW1[4 * 64 + lane], xa);  xb = fmaf(a4, sW1[4 * 64 + lane + 32], xb);
    sx1[wl][lane]      = fmaxf(xa, 0.f);
    sx1[wl][lane + 32] = fmaxf(xb, 0.f);
    __syncwarp();

    // hs2[lane] = (x1 @ W2[:,lane]) * d
    float s = 0.f;
#pragma unroll 16
    for (int k = 0; k < 64; k++)
        s = fmaf(sx1[wl][k], sW2[k * 32 + lane], s);
    float hs = s * d;
    g_hs2 [node * 32 + lane] = hs;
    g_acc2[node * 32 + lane] = hs;   // self-loop init
}

// ---------------------------------------------------------------------------
// Layer-2 edge scatter (32 floats): 8 threads per edge, red.v4 each.
// ---------------------------------------------------------------------------
__global__ void k_scatter2() {
    long long t = (long long)blockIdx.x * blockDim.x + threadIdx.x;
    if (t >= (long long)NE * 8) return;
    int e = (int)(t >> 3);
    int p = ((int)t & 7) * 4;
    int2 ed = g_edge[e];
    float4 v = *(const float4*)&g_hs2[ed.x * 32 + p];
    float* a = &g_acc2[ed.y * 32 + p];
    asm volatile("red.global.add.v4.f32 [%0], {%1,%2,%3,%4};"
                 :: "l"(a), "f"(v.x), "f"(v.y), "f"(v.z), "f"(v.w) : "memory");
}

// ---------------------------------------------------------------------------
// Finalize layer 2 + fused MLP head:
// x2 = relu(acc2*dinv + b2); x3 = relu(x2@fcW1 + fcb1); out = x3@fcW2 + fcb2
// ---------------------------------------------------------------------------
__global__ void k_final2(const float* __restrict__ b2,
                         const float* __restrict__ fcW1,
                         const float* __restrict__ fcb1,
                         const float* __restrict__ fcW2,
                         const float* __restrict__ fcb2,
                         float* __restrict__ out) {
    int i = blockIdx.x * blockDim.x + threadIdx.x;
    if (i >= NN) return;
    float d = g_dinv[i];

    float x2[32];
#pragma unroll
    for (int j = 0; j < 32; j += 4) {
        float4 a = *(const float4*)&g_acc2[i * 32 + j];
        x2[j + 0] = fmaxf(fmaf(a.x, d, b2[j + 0]), 0.f);
        x2[j + 1] = fmaxf(fmaf(a.y, d, b2[j + 1]), 0.f);
        x2[j + 2] = fmaxf(fmaf(a.z, d, b2[j + 2]), 0.f);
        x2[j + 3] = fmaxf(fmaf(a.w, d, b2[j + 3]), 0.f);
    }

    float x3[16];
#pragma unroll
    for (int m = 0; m < 16; m++) x3[m] = fcb1[m];
#pragma unroll
    for (int j = 0; j < 32; j++) {
        float xv = x2[j];
#pragma unroll
        for (int m = 0; m < 16; m++)
            x3[m] = fmaf(xv, fcW1[j * 16 + m], x3[m]);
    }
#pragma unroll
    for (int m = 0; m < 16; m++) x3[m] = fmaxf(x3[m], 0.f);

    float o0 = fcb2[0], o1 = fcb2[1];
#pragma unroll
    for (int m = 0; m < 16; m++) {
        o0 = fmaf(x3[m], fcW2[m * 2 + 0], o0);
        o1 = fmaf(x3[m], fcW2[m * 2 + 1], o1);
    }
    out[i * 2 + 0] = o0;
    out[i * 2 + 1] = o1;
}

// ---------------------------------------------------------------------------
// Launch
// ---------------------------------------------------------------------------
extern "C" void kernel_launch(void* const* d_in, const int* in_sizes, int n_in,
                              void* d_out, int out_size) {
    const float* edge_attr = (const float*)d_in[0];
    const void*  edge_idx  = d_in[1];
    const float* W1   = (const float*)d_in[2];
    const float* b1   = (const float*)d_in[3];
    const float* W2   = (const float*)d_in[4];
    const float* b2   = (const float*)d_in[5];
    const float* fcW1 = (const float*)d_in[6];
    const float* fcb1 = (const float*)d_in[7];
    const float* fcW2 = (const float*)d_in[8];
    const float* fcb2 = (const float*)d_in[9];
    float* out = (float*)d_out;

    const int T = 256;

    k_detect <<<1, 32>>>((const int*)edge_idx);
    k_initdeg<<<(NN + T - 1) / T, T>>>();
    k_prep   <<<(NE + T - 1) / T, T>>>(edge_idx);
    k_dinv   <<<(NN + T - 1) / T, T>>>();

    // Layer 1: aggregate raw 5-dim features, then transform (fused in k_mid)
    k_prescale<<<(NN + T - 1) / T, T>>>(edge_attr);
    k_scatter1<<<(NE + T - 1) / T, T>>>();
    k_mid     <<<NN / 8, 256>>>(W1, b1, W2);

    // Layer 2: scatter transformed 32-dim features
    k_scatter2<<<(int)(((long long)NE * 8 + T - 1) / T), T>>>();

    // Finalize + MLP head
    k_final2<<<(NN + T - 1) / T, T>>>(b2, fcW1, fcb1, fcW2, fcb2, out);
}